// round 6
// baseline (speedup 1.0000x reference)
#include <cuda_runtime.h>
#include <cstdint>

// HoyerSparsityLoss: N=1024 anchors, 1024 pos + 1024 neg targets, D=256.
// hoyer = (16 - l1/l2)/15, T=0.05. loss_i = log(sum_t exp(h/T)) - h_ii/T.
// Fused single kernel. FFMA-imm (rt1) for diff & l1-accum; 3-reg FFMA for l2.
// R6 change: 3 blocks/SM (reg cap 85) to cover the measured 28.5% issue-idle.

#define TI    64
#define TJ    64
#define DK    32
#define DVAL  256
#define NANCH 1024
#define NBLK  512          // 16 i-tiles x 32 j-tiles

__device__ float    g_rowsum[NANCH];  // zero-init at load; last block re-zeroes
__device__ float    g_diag[NANCH];
__device__ unsigned g_count;          // zero-init; last block resets

// 1 ulp below 1.0: forces FFMA-imm (ptxas cannot fold to FADD). d error ~6e-8 rel.
#define C_NEG (-0.99999994f)

#define CP_ASYNC16(smem_u32, gptr) \
    asm volatile("cp.async.cg.shared.global [%0], [%1], 16;" :: "r"(smem_u32), "l"(gptr))
#define CP_COMMIT() asm volatile("cp.async.commit_group;")
#define CP_WAIT(n)  asm volatile("cp.async.wait_group %0;" :: "n"(n))

__global__ __launch_bounds__(256, 3) void hoyer_k(const float* __restrict__ anchor,
                                                  const float* __restrict__ pos,
                                                  const float* __restrict__ neg,
                                                  float* __restrict__ out) {
    __shared__ float4 As[2][8][TI];   // 16 KB
    __shared__ float4 Bs[2][8][TJ];   // 16 KB  (32 KB/block -> 3 blocks = 96 KB/SM)

    const int bi = blockIdx.x;             // 16 i-tiles
    const int bj = blockIdx.y;             // 32 j-tiles (16 pos + 16 neg)
    const bool is_pos = (bj < 16);
    const float* tgt = is_pos ? pos : neg;
    const int joff = (is_pos ? bj : bj - 16) * TJ;
    const int ioff = bi * TI;
    const int tid = threadIdx.x;
    const int tx = tid & 15;               // j = tx + 16*jj
    const int ty = tid >> 4;               // i = ty + 16*ii

    float l1[4][4], l2[4][4];
#pragma unroll
    for (int ii = 0; ii < 4; ++ii)
#pragma unroll
        for (int jj = 0; jj < 4; ++jj) { l1[ii][jj] = 0.0f; l2[ii][jj] = 0.0f; }

    auto load_chunk = [&](int c, int buf) {
#pragma unroll
        for (int r = 0; r < 2; ++r) {
            const int idx = tid + r * 256;
            const int row = idx & 63, c4 = idx >> 6;
            const float* ga = anchor + (size_t)(ioff + row) * DVAL + c * DK + c4 * 4;
            CP_ASYNC16((unsigned)__cvta_generic_to_shared(&As[buf][c4][row]), ga);
            const float* gb = tgt + (size_t)(joff + row) * DVAL + c * DK + c4 * 4;
            CP_ASYNC16((unsigned)__cvta_generic_to_shared(&Bs[buf][c4][row]), gb);
        }
    };

    load_chunk(0, 0);
    CP_COMMIT();

    for (int c = 0; c < DVAL / DK; ++c) {
        const int buf = c & 1;
        if (c + 1 < DVAL / DK) { load_chunk(c + 1, buf ^ 1); CP_COMMIT(); CP_WAIT(1); }
        else                   { CP_WAIT(0); }
        __syncthreads();

#pragma unroll
        for (int c4 = 0; c4 < 8; ++c4) {
            float4 bv[4];
#pragma unroll
            for (int jj = 0; jj < 4; ++jj) bv[jj] = Bs[buf][c4][tx + 16 * jj];
#pragma unroll
            for (int ii = 0; ii < 4; ++ii) {
                const float4 av = As[buf][c4][ty + 16 * ii];   // broadcast
                const float* af = (const float*)&av;
#pragma unroll
                for (int jj = 0; jj < 4; ++jj) {
                    const float* bf = (const float*)&bv[jj];
#pragma unroll
                    for (int dk = 0; dk < 4; ++dk) {
                        const float d = fmaf(bf[dk], C_NEG, af[dk]);   // FFMA-imm (rt1)
                        l2[ii][jj] = fmaf(d, d, l2[ii][jj]);           // FFMA     (rt2)
                        l1[ii][jj] = fmaf(fabsf(d), 2.0f, l1[ii][jj]); // FFMA-imm (rt1)
                    }
                }
            }
        }
        __syncthreads();
    }

    // Epilogue: hoyer -> exp -> row sums (+ diagonal on pos tiles). l1 carries x2.
    const float inv15 = 1.0f / 15.0f;
#pragma unroll
    for (int ii = 0; ii < 4; ++ii) {
        const int gi = ioff + ty + 16 * ii;
        float rsum = 0.0f;
#pragma unroll
        for (int jj = 0; jj < 4; ++jj) {
            // l2 ~ 510 here; 1e-8 eps is relatively ~4e-10 -> dropped.
            const float hy = (16.0f - l1[ii][jj] * 0.5f * rsqrtf(l2[ii][jj])) * inv15;
            rsum += __expf(hy * 20.0f);     // hy / T, T = 0.05
            if (is_pos && (joff + tx + 16 * jj) == gi) g_diag[gi] = hy;  // unique writer
        }
#pragma unroll
        for (int m = 1; m < 16; m <<= 1)
            rsum += __shfl_xor_sync(0xffffffffu, rsum, m);
        if (tx == 0) atomicAdd(&g_rowsum[gi], rsum);
    }

    // ---- last-block final reduction (fused; no separate kernel launch) ----
    __shared__ bool is_last;
    __threadfence();
    if (tid == 0) is_last = (atomicAdd(&g_count, 1u) == NBLK - 1);
    __syncthreads();
    if (!is_last) return;
    __threadfence();   // acquire: all blocks' rowsum/diag now visible

    float acc = 0.0f;
#pragma unroll
    for (int r = 0; r < 4; ++r) {
        const int i = tid + r * 256;
        acc += __logf(g_rowsum[i]) - g_diag[i] * 20.0f;
        g_rowsum[i] = 0.0f;               // reset for next graph replay
    }
#pragma unroll
    for (int m = 16; m > 0; m >>= 1) acc += __shfl_xor_sync(0xffffffffu, acc, m);

    __shared__ float warp_part[8];
    if ((tid & 31) == 0) warp_part[tid >> 5] = acc;
    __syncthreads();
    if (tid < 32) {
        float w = (tid < 8) ? warp_part[tid] : 0.0f;
#pragma unroll
        for (int m = 4; m > 0; m >>= 1) w += __shfl_xor_sync(0xffffffffu, w, m);
        if (tid == 0) { out[0] = w * (1.0f / 1024.0f); g_count = 0; }
    }
}

extern "C" void kernel_launch(void* const* d_in, const int* in_sizes, int n_in,
                              void* d_out, int out_size) {
    const float* anchor = (const float*)d_in[0];
    const float* pos    = (const float*)d_in[1];
    const float* neg    = (const float*)d_in[2];

    dim3 grid(NANCH / TI, 32);   // 16 x (16 pos + 16 neg) = 512 blocks
    hoyer_k<<<grid, 256>>>(anchor, pos, neg, (float*)d_out);
}